// round 2
// baseline (speedup 1.0000x reference)
#include <cuda_runtime.h>
#include <math.h>

// ---------------------------------------------------------------------------
// Problem constants
// ---------------------------------------------------------------------------
#define BSZ 16
#define CCH 128
#define PP  48
#define NN  2304              // PP*PP
#define C8V 16                // CCH/8
#define BCN (BSZ*CCH*NN)      // 2048*2304 = 4,718,592

// ---------------------------------------------------------------------------
// Scratch (device globals — allocation-free)
// ---------------------------------------------------------------------------
__device__ float g_xn  [BSZ*CCH*NN];
__device__ float g_h   [BSZ*CCH*NN];
__device__ float g_feat[BSZ*CCH*NN];      // features, later reused as front_res
__device__ float g_v   [BSZ*CCH*NN];
__device__ float g_V   [BSZ*CCH*NN];
__device__ float g_T   [BSZ*CCH*NN];
__device__ float g_q   [BSZ*C8V*NN];
__device__ float g_k   [BSZ*C8V*NN];
__device__ float g_E   [(size_t)BSZ*NN*NN];   // 340 MB attention matrix
__device__ float g_mean[CCH];
__device__ float g_rstd[CCH];

// ---------------------------------------------------------------------------
// BatchNorm statistics: one block per channel, reduce over B*N samples
// ---------------------------------------------------------------------------
__global__ void bn_stats(const float* __restrict__ x) {
    int c = blockIdx.x;
    float s = 0.f, s2 = 0.f;
    for (int b = 0; b < BSZ; b++) {
        const float* p = x + ((size_t)b*CCH + c)*NN;
        for (int i = threadIdx.x; i < NN; i += blockDim.x) {
            float v = p[i];
            s += v; s2 += v*v;
        }
    }
    __shared__ float rs[8], rs2[8];
    for (int o = 16; o; o >>= 1) {
        s  += __shfl_xor_sync(0xffffffffu, s,  o);
        s2 += __shfl_xor_sync(0xffffffffu, s2, o);
    }
    int w = threadIdx.x >> 5, l = threadIdx.x & 31;
    if (l == 0) { rs[w] = s; rs2[w] = s2; }
    __syncthreads();
    if (threadIdx.x == 0) {
        float ts = 0.f, ts2 = 0.f;
        for (int t = 0; t < 8; t++) { ts += rs[t]; ts2 += rs2[t]; }
        float inv = 1.0f / (float)(BSZ*NN);
        float m   = ts * inv;
        float var = ts2 * inv - m*m;
        g_mean[c] = m;
        g_rstd[c] = rsqrtf(var + 1e-5f);
    }
}

// ---------------------------------------------------------------------------
// BatchNorm apply (elementwise)
// ---------------------------------------------------------------------------
__global__ void bn_apply(const float* __restrict__ x, const float* __restrict__ g,
                         const float* __restrict__ b, float* __restrict__ y) {
    int i = blockIdx.x * blockDim.x + threadIdx.x;
    if (i >= BCN) return;
    int c = (i / NN) % CCH;
    y[i] = (x[i] - g_mean[c]) * g_rstd[c] * g[c] + b[c];
}

// ---------------------------------------------------------------------------
// Generic batched SGEMM:  C = A * B^T  (TRANSB=true,  B is (N,K) K-major)
//                         C = A * B    (TRANSB=false, B is (K,N) n-major,
//                                       with optional row-concat B1|B2 at K1)
// BM=BN=128, BK=16, 256 threads, 8x8 microtile per thread.
// biasMode: 0 none, 1 per output column, 2 per output row. relu optional.
// ---------------------------------------------------------------------------
template<bool TRANSB>
__global__ void __launch_bounds__(256)
gemm(const float* __restrict__ A,
     const float* __restrict__ B1, const float* __restrict__ B2, int K1,
     float* __restrict__ C, int M, int N, int K,
     long long sA, long long sB1, long long sB2, long long sC,
     const float* __restrict__ bias, int biasMode, int relu)
{
    const int BK = 16;
    __shared__ float As[BK][128];
    __shared__ float Bs[BK][128];

    int bz = blockIdx.z;
    A += bz * sA;
    const float* B1p = B1 + bz * sB1;
    const float* B2p = B2 + bz * sB2;
    C += bz * sC;

    int m0 = blockIdx.y * 128;
    int n0 = blockIdx.x * 128;
    int tid = threadIdx.x;
    int tx = tid & 15;       // 16 col-threads
    int ty = tid >> 4;       // 16 row-threads

    float acc[8][8];
#pragma unroll
    for (int i = 0; i < 8; i++)
#pragma unroll
        for (int j = 0; j < 8; j++) acc[i][j] = 0.f;

    for (int k0 = 0; k0 < K; k0 += BK) {
        // ---- load A tile (128 x 16), transpose into As[k][m]
#pragma unroll
        for (int it = 0; it < 2; it++) {
            int f   = tid * 2 + it;       // float4 index 0..511
            int row = f >> 2;             // 0..127
            int c4  = (f & 3) * 4;        // 0,4,8,12
            int mg  = m0 + row;
            float4 v = make_float4(0.f, 0.f, 0.f, 0.f);
            if (mg < M) v = *(const float4*)(A + (size_t)mg * K + k0 + c4);
            As[c4+0][row] = v.x; As[c4+1][row] = v.y;
            As[c4+2][row] = v.z; As[c4+3][row] = v.w;
        }
        // ---- load B tile
        if (TRANSB) {
#pragma unroll
            for (int it = 0; it < 2; it++) {
                int f   = tid * 2 + it;
                int row = f >> 2;
                int c4  = (f & 3) * 4;
                int ng  = n0 + row;
                float4 v = *(const float4*)(B1p + (size_t)ng * K + k0 + c4);
                Bs[c4+0][row] = v.x; Bs[c4+1][row] = v.y;
                Bs[c4+2][row] = v.z; Bs[c4+3][row] = v.w;
            }
        } else {
#pragma unroll
            for (int it = 0; it < 2; it++) {
                int f  = tid * 2 + it;    // 512 float4: 16 rows x 32 col4
                int kr = f >> 5;          // 0..15
                int c4 = (f & 31) * 4;    // 0..124
                int kg = k0 + kr;
                const float* src = (kg < K1)
                    ? (B1p + (size_t)kg * N + n0 + c4)
                    : (B2p + (size_t)(kg - K1) * N + n0 + c4);
                *(float4*)&Bs[kr][c4] = *(const float4*)src;
            }
        }
        __syncthreads();

#pragma unroll
        for (int kk = 0; kk < BK; kk++) {
            float4 a0 = *(const float4*)&As[kk][ty*8];
            float4 a1 = *(const float4*)&As[kk][ty*8+4];
            float4 b0 = *(const float4*)&Bs[kk][tx*8];
            float4 b1 = *(const float4*)&Bs[kk][tx*8+4];
            float a[8] = {a0.x,a0.y,a0.z,a0.w,a1.x,a1.y,a1.z,a1.w};
            float b[8] = {b0.x,b0.y,b0.z,b0.w,b1.x,b1.y,b1.z,b1.w};
#pragma unroll
            for (int i = 0; i < 8; i++)
#pragma unroll
                for (int j = 0; j < 8; j++)
                    acc[i][j] = fmaf(a[i], b[j], acc[i][j]);
        }
        __syncthreads();
    }

    // ---- epilogue
#pragma unroll
    for (int i = 0; i < 8; i++) {
        int mg = m0 + ty*8 + i;
        if (mg >= M) break;
#pragma unroll
        for (int j = 0; j < 8; j++) {
            int ng = n0 + tx*8 + j;
            float v = acc[i][j];
            if (biasMode == 1)      v += bias[ng];
            else if (biasMode == 2) v += bias[mg];
            if (relu) v = fmaxf(v, 0.f);
            C[(size_t)mg * N + ng] = v;
        }
    }
}

// ---------------------------------------------------------------------------
// Attention scores + softmax:
//   E[b,i,j] = softmax_j( sum_c k[b,c,i]*q[b,c,j] / sqrt(128) )
// One block per (batch, 16-row i-block). Scores kept in dynamic smem.
// ---------------------------------------------------------------------------
__global__ void __launch_bounds__(256)
attn_scores(const float* __restrict__ q, const float* __restrict__ kmat,
            float* __restrict__ E)
{
    extern __shared__ float sc[];      // [16][NN]
    __shared__ float Kv[16][17];       // [c][ii]
    __shared__ float red[8];

    int b  = blockIdx.y;
    int i0 = blockIdx.x * 16;
    int tid = threadIdx.x;

    const float* qb = q    + (size_t)b * C8V * NN;
    const float* kb = kmat + (size_t)b * C8V * NN;

    {
        int c = tid >> 4, ii = tid & 15;   // 256 threads = 16x16
        Kv[c][ii] = kb[c * NN + i0 + ii];
    }
    __syncthreads();

    const float scale = rsqrtf(128.f);
    for (int j = tid; j < NN; j += 256) {
        float qv[16];
#pragma unroll
        for (int c = 0; c < 16; c++) qv[c] = qb[c * NN + j];
#pragma unroll
        for (int ii = 0; ii < 16; ii++) {
            float s = 0.f;
#pragma unroll
            for (int c = 0; c < 16; c++) s = fmaf(Kv[c][ii], qv[c], s);
            sc[ii * NN + j] = s * scale;
        }
    }
    __syncthreads();

    int w = tid >> 5, l = tid & 31;
    for (int ii = 0; ii < 16; ii++) {
        float* row = sc + ii * NN;
        // max
        float m = -1e30f;
        for (int j = tid; j < NN; j += 256) m = fmaxf(m, row[j]);
        for (int o = 16; o; o >>= 1) m = fmaxf(m, __shfl_xor_sync(0xffffffffu, m, o));
        if (l == 0) red[w] = m;
        __syncthreads();
        m = red[0];
#pragma unroll
        for (int t = 1; t < 8; t++) m = fmaxf(m, red[t]);
        // exp + sum
        float s = 0.f;
        for (int j = tid; j < NN; j += 256) {
            float e = __expf(row[j] - m);
            row[j] = e;
            s += e;
        }
        for (int o = 16; o; o >>= 1) s += __shfl_xor_sync(0xffffffffu, s, o);
        __syncthreads();
        if (l == 0) red[w] = s;
        __syncthreads();
        s = 0.f;
#pragma unroll
        for (int t = 0; t < 8; t++) s += red[t];
        float inv = 1.f / s;
        float* Eb = E + ((size_t)b * NN + i0 + ii) * NN;
        for (int j = tid; j < NN; j += 256) Eb[j] = row[j] * inv;
        __syncthreads();
    }
}

// ---------------------------------------------------------------------------
// Launch
// ---------------------------------------------------------------------------
extern "C" void kernel_launch(void* const* d_in, const int* in_sizes, int n_in,
                              void* d_out, int out_size)
{
    const float* front_x = (const float*)d_in[0];
    const float* bn1_g   = (const float*)d_in[1];
    const float* bn1_b   = (const float*)d_in[2];
    const float* tm1_w1  = (const float*)d_in[3];
    const float* tm1_b1  = (const float*)d_in[4];
    const float* tm1_w2  = (const float*)d_in[5];
    const float* tm1_b2  = (const float*)d_in[6];
    const float* q_w     = (const float*)d_in[7];
    const float* q_b     = (const float*)d_in[8];
    const float* k_w     = (const float*)d_in[9];
    const float* k_b     = (const float*)d_in[10];
    const float* v_w     = (const float*)d_in[11];
    const float* v_b     = (const float*)d_in[12];
    const float* m1_w    = (const float*)d_in[13];
    const float* m1_b    = (const float*)d_in[14];
    const float* bn2_g   = (const float*)d_in[15];
    const float* bn2_b   = (const float*)d_in[16];
    const float* tm2_w1  = (const float*)d_in[17];
    const float* tm2_b1  = (const float*)d_in[18];
    const float* tm2_w2  = (const float*)d_in[19];
    const float* tm2_b2  = (const float*)d_in[20];
    const float* m2_w    = (const float*)d_in[21];
    const float* m2_b    = (const float*)d_in[22];
    float* out = (float*)d_out;

    float *xn, *h, *feat, *vbuf, *Vbuf, *Tbuf, *qb, *kb, *Eb;
    cudaGetSymbolAddress((void**)&xn,   g_xn);
    cudaGetSymbolAddress((void**)&h,    g_h);
    cudaGetSymbolAddress((void**)&feat, g_feat);
    cudaGetSymbolAddress((void**)&vbuf, g_v);
    cudaGetSymbolAddress((void**)&Vbuf, g_V);
    cudaGetSymbolAddress((void**)&Tbuf, g_T);
    cudaGetSymbolAddress((void**)&qb,   g_q);
    cudaGetSymbolAddress((void**)&kb,   g_k);
    cudaGetSymbolAddress((void**)&Eb,   g_E);

    cudaFuncSetAttribute(attn_scores,
                         cudaFuncAttributeMaxDynamicSharedMemorySize,
                         16 * NN * (int)sizeof(float));

    const long long BN0 = 0;
    const long long sFeat = (long long)CCH * NN;   // per-batch stride of (B,128,N)
    const long long sQK   = (long long)C8V * NN;
    const long long sE    = (long long)NN * NN;

    dim3 gTM(NN/128, (BSZ*CCH)/128, 1);   // 18 x 16
    dim3 gCV(NN/128, 1, BSZ);             // 18 x 1 x 16
    int  nApply = (BCN + 255) / 256;

    // 1. BN1
    bn_stats<<<CCH, 256>>>(front_x);
    bn_apply<<<nApply, 256>>>(front_x, bn1_g, bn1_b, xn);
    // 2. TM1: two (2048,2304)x(2304,2304)^T GEMMs with bias(col)+relu
    gemm<true><<<gTM, 256>>>(xn, tm1_w1, tm1_w1, NN, h,    BSZ*CCH, NN, NN,
                             BN0, BN0, BN0, BN0, tm1_b1, 1, 1);
    gemm<true><<<gTM, 256>>>(h,  tm1_w2, tm1_w2, NN, feat, BSZ*CCH, NN, NN,
                             BN0, BN0, BN0, BN0, tm1_b2, 1, 1);
    // 3. q / k / v 1x1 convs (W * X_b), bias per output row
    gemm<false><<<gCV, 256>>>(q_w, feat, feat, CCH, qb,   C8V, NN, CCH,
                              BN0, sFeat, sFeat, sQK,   q_b, 2, 0);
    gemm<false><<<gCV, 256>>>(k_w, feat, feat, CCH, kb,   C8V, NN, CCH,
                              BN0, sFeat, sFeat, sQK,   k_b, 2, 0);
    gemm<false><<<gCV, 256>>>(v_w, feat, feat, CCH, vbuf, CCH, NN, CCH,
                              BN0, sFeat, sFeat, sFeat, v_b, 2, 0);
    // 4. attention scores + softmax -> g_E
    attn_scores<<<dim3(NN/16, BSZ), 256, 16 * NN * sizeof(float)>>>(qb, kb, Eb);
    // 5. V = v @ E^T  (batched)
    gemm<true><<<gCV, 256>>>(vbuf, Eb, Eb, NN, Vbuf, CCH, NN, NN,
                             sFeat, sE, sE, sFeat, (const float*)nullptr, 0, 0);
    // 6. m1 conv over concat(feat, V)
    gemm<false><<<gCV, 256>>>(m1_w, feat, Vbuf, CCH, Tbuf, CCH, NN, 2*CCH,
                              BN0, sFeat, sFeat, sFeat, m1_b, 2, 0);
    // 7. BN2
    bn_stats<<<CCH, 256>>>(Tbuf);
    bn_apply<<<nApply, 256>>>(Tbuf, bn2_g, bn2_b, xn);
    // 8. TM2 (feat reused as front_res)
    gemm<true><<<gTM, 256>>>(xn, tm2_w1, tm2_w1, NN, h,    BSZ*CCH, NN, NN,
                             BN0, BN0, BN0, BN0, tm2_b1, 1, 1);
    gemm<true><<<gTM, 256>>>(h,  tm2_w2, tm2_w2, NN, feat, BSZ*CCH, NN, NN,
                             BN0, BN0, BN0, BN0, tm2_b2, 1, 1);
    // 9. m2 conv over concat(front_res, V) -> output
    gemm<false><<<gCV, 256>>>(m2_w, feat, Vbuf, CCH, out, CCH, NN, 2*CCH,
                              BN0, sFeat, sFeat, sFeat, m2_b, 2, 0);
}

// round 3
// speedup vs baseline: 1.7674x; 1.7674x over previous
#include <cuda_runtime.h>
#include <math.h>
#include <stdint.h>

// ---------------------------------------------------------------------------
// Problem constants
// ---------------------------------------------------------------------------
#define BSZ 16
#define CCH 128
#define PP  48
#define NN  2304              // PP*PP
#define C8V 16                // CCH/8
#define BCN (BSZ*CCH*NN)      // 4,718,592

// ---------------------------------------------------------------------------
// Scratch (device globals — allocation-free)
// ---------------------------------------------------------------------------
__device__ float g_xn  [BSZ*CCH*NN];
__device__ float g_h   [BSZ*CCH*NN];
__device__ float g_feat[BSZ*CCH*NN];
__device__ float g_v   [BSZ*CCH*NN];
__device__ float g_V   [BSZ*CCH*NN];
__device__ float g_T   [BSZ*CCH*NN];
__device__ float g_q   [BSZ*C8V*NN];
__device__ float g_k   [BSZ*C8V*NN];
__device__ float g_E   [(size_t)BSZ*NN*NN];   // 340 MB attention matrix
__device__ float g_mean[CCH];
__device__ float g_rstd[CCH];

// ---------------------------------------------------------------------------
// Fast exp on the FMA pipe (no MUFU). |rel err| < 2e-7 for the ranges here.
// ---------------------------------------------------------------------------
__device__ __forceinline__ float fexp(float x) {
    const float L2E = 1.4426950408889634f;
    float t = fmaf(x, L2E, 12582912.0f);       // round-to-nearest via magic
    float n = t - 12582912.0f;
    float f = fmaf(x, L2E, -n);                // frac in [-0.5, 0.5]
    float z = f * 0.6931471805599453f;
    float p = 1.3888889e-3f;                   // 1/720
    p = fmaf(p, z, 8.3333333e-3f);             // 1/120
    p = fmaf(p, z, 4.1666668e-2f);             // 1/24
    p = fmaf(p, z, 1.6666667e-1f);             // 1/6
    p = fmaf(p, z, 0.5f);
    p = fmaf(p, z, 1.0f);
    p = fmaf(p, z, 1.0f);
    return p * __int_as_float(((int)n + 127) << 23);
}

__device__ __forceinline__ float tf32r(float x) {
    uint32_t r;
    asm("cvt.rna.tf32.f32 %0, %1;" : "=r"(r) : "f"(x));
    return __uint_as_float(r);
}

// ---------------------------------------------------------------------------
// BatchNorm statistics
// ---------------------------------------------------------------------------
__global__ void bn_stats(const float* __restrict__ x) {
    int c = blockIdx.x;
    float s = 0.f, s2 = 0.f;
    for (int b = 0; b < BSZ; b++) {
        const float* p = x + ((size_t)b*CCH + c)*NN;
        for (int i = threadIdx.x; i < NN; i += blockDim.x) {
            float v = p[i];
            s += v; s2 += v*v;
        }
    }
    __shared__ float rs[8], rs2[8];
    for (int o = 16; o; o >>= 1) {
        s  += __shfl_xor_sync(0xffffffffu, s,  o);
        s2 += __shfl_xor_sync(0xffffffffu, s2, o);
    }
    int w = threadIdx.x >> 5, l = threadIdx.x & 31;
    if (l == 0) { rs[w] = s; rs2[w] = s2; }
    __syncthreads();
    if (threadIdx.x == 0) {
        float ts = 0.f, ts2 = 0.f;
        for (int t = 0; t < 8; t++) { ts += rs[t]; ts2 += rs2[t]; }
        float inv = 1.0f / (float)(BSZ*NN);
        float m   = ts * inv;
        float var = ts2 * inv - m*m;
        g_mean[c] = m;
        g_rstd[c] = rsqrtf(var + 1e-5f);
    }
}

__global__ void bn_apply(const float* __restrict__ x, const float* __restrict__ g,
                         const float* __restrict__ b, float* __restrict__ y) {
    int i = blockIdx.x * blockDim.x + threadIdx.x;
    if (i >= BCN) return;
    int c = (i / NN) % CCH;
    y[i] = (x[i] - g_mean[c]) * g_rstd[c] * g[c] + b[c];
}

// ---------------------------------------------------------------------------
// Tensor-core TF32 GEMM:  C = A(M,K) * B(N,K)^T   (both K-major)
// Requires M%128==0, N%128==0, K%16==0 (true for all call sites).
// 256 threads = 8 warps (4x2); warp tile 32x64 via m16n8k8.
// biasCol: optional per-output-column bias. relu optional.
// ---------------------------------------------------------------------------
__global__ void __launch_bounds__(256)
gemm_tc(const float* __restrict__ A, const float* __restrict__ B,
        float* __restrict__ C, int M, int N, int K,
        long long sA, long long sB, long long sC,
        const float* __restrict__ biasCol, int relu)
{
    __shared__ float As[16][136];
    __shared__ float Bs[16][136];

    int bz = blockIdx.z;
    A += bz * sA; B += bz * sB; C += bz * sC;

    int m0 = blockIdx.y * 128;
    int n0 = blockIdx.x * 128;
    int tid  = threadIdx.x;
    int wid  = tid >> 5, lane = tid & 31;
    int mw   = (wid & 3) * 32;          // warp row offset
    int nw   = (wid >> 2) * 64;         // warp col offset
    int g    = lane >> 2;               // 0..7
    int kq   = lane & 3;                // 0..3

    float acc[2][8][4];
#pragma unroll
    for (int mt = 0; mt < 2; mt++)
#pragma unroll
        for (int nt = 0; nt < 8; nt++)
#pragma unroll
            for (int r = 0; r < 4; r++) acc[mt][nt][r] = 0.f;

    for (int k0 = 0; k0 < K; k0 += 16) {
        // ---- load tiles (each thread: 2 float4 from A, 2 from B), tf32-round
#pragma unroll
        for (int it = 0; it < 2; it++) {
            int f   = tid * 2 + it;       // 0..511
            int row = f >> 2;             // 0..127
            int c4  = (f & 3) * 4;        // 0,4,8,12
            float4 va = *(const float4*)(A + (size_t)(m0 + row) * K + k0 + c4);
            float4 vb = *(const float4*)(B + (size_t)(n0 + row) * K + k0 + c4);
            As[c4+0][row] = tf32r(va.x); As[c4+1][row] = tf32r(va.y);
            As[c4+2][row] = tf32r(va.z); As[c4+3][row] = tf32r(va.w);
            Bs[c4+0][row] = tf32r(vb.x); Bs[c4+1][row] = tf32r(vb.y);
            Bs[c4+2][row] = tf32r(vb.z); Bs[c4+3][row] = tf32r(vb.w);
        }
        __syncthreads();

#pragma unroll
        for (int ks = 0; ks < 16; ks += 8) {
            int kA = ks + kq;
            uint32_t a[2][4], b[8][2];
#pragma unroll
            for (int mt = 0; mt < 2; mt++) {
                int mb = mw + mt * 16;
                a[mt][0] = __float_as_uint(As[kA    ][mb + g    ]);
                a[mt][1] = __float_as_uint(As[kA    ][mb + g + 8]);
                a[mt][2] = __float_as_uint(As[kA + 4][mb + g    ]);
                a[mt][3] = __float_as_uint(As[kA + 4][mb + g + 8]);
            }
#pragma unroll
            for (int nt = 0; nt < 8; nt++) {
                int nb = nw + nt * 8 + g;
                b[nt][0] = __float_as_uint(Bs[kA    ][nb]);
                b[nt][1] = __float_as_uint(Bs[kA + 4][nb]);
            }
#pragma unroll
            for (int mt = 0; mt < 2; mt++)
#pragma unroll
                for (int nt = 0; nt < 8; nt++) {
                    asm volatile(
                        "mma.sync.aligned.m16n8k8.row.col.f32.tf32.tf32.f32 "
                        "{%0,%1,%2,%3}, {%4,%5,%6,%7}, {%8,%9}, {%0,%1,%2,%3};"
                        : "+f"(acc[mt][nt][0]), "+f"(acc[mt][nt][1]),
                          "+f"(acc[mt][nt][2]), "+f"(acc[mt][nt][3])
                        : "r"(a[mt][0]), "r"(a[mt][1]), "r"(a[mt][2]), "r"(a[mt][3]),
                          "r"(b[nt][0]), "r"(b[nt][1]));
                }
        }
        __syncthreads();
    }

    // ---- epilogue
    int c2 = (lane & 3) * 2;
#pragma unroll
    for (int mt = 0; mt < 2; mt++) {
        int row0 = m0 + mw + mt * 16 + g;
#pragma unroll
        for (int nt = 0; nt < 8; nt++) {
            int col = n0 + nw + nt * 8 + c2;
            float b0 = 0.f, b1 = 0.f;
            if (biasCol) { b0 = biasCol[col]; b1 = biasCol[col + 1]; }
            float v0 = acc[mt][nt][0] + b0;
            float v1 = acc[mt][nt][1] + b1;
            float v2 = acc[mt][nt][2] + b0;
            float v3 = acc[mt][nt][3] + b1;
            if (relu) {
                v0 = fmaxf(v0, 0.f); v1 = fmaxf(v1, 0.f);
                v2 = fmaxf(v2, 0.f); v3 = fmaxf(v3, 0.f);
            }
            *(float2*)(C + (size_t)row0 * N + col)       = make_float2(v0, v1);
            *(float2*)(C + (size_t)(row0 + 8) * N + col) = make_float2(v2, v3);
        }
    }
}

// ---------------------------------------------------------------------------
// SIMT SGEMM, C = A * B (B n-major, optional row-concat B1|B2 at K1).
// Used only for the small 1x1 convs (K<=256). biasRow per output row.
// ---------------------------------------------------------------------------
__global__ void __launch_bounds__(256)
gemm_nt(const float* __restrict__ A,
        const float* __restrict__ B1, const float* __restrict__ B2, int K1,
        float* __restrict__ C, int M, int N, int K,
        long long sB1, long long sB2, long long sC,
        const float* __restrict__ biasRow, int relu)
{
    const int BK = 16;
    __shared__ float As[BK][128];
    __shared__ float Bs[BK][128];

    int bz = blockIdx.z;
    const float* B1p = B1 + bz * sB1;
    const float* B2p = B2 + bz * sB2;
    C += bz * sC;

    int m0 = blockIdx.y * 128;
    int n0 = blockIdx.x * 128;
    int tid = threadIdx.x;
    int tx = tid & 15;
    int ty = tid >> 4;

    float acc[8][8];
#pragma unroll
    for (int i = 0; i < 8; i++)
#pragma unroll
        for (int j = 0; j < 8; j++) acc[i][j] = 0.f;

    for (int k0 = 0; k0 < K; k0 += BK) {
#pragma unroll
        for (int it = 0; it < 2; it++) {
            int f   = tid * 2 + it;
            int row = f >> 2;
            int c4  = (f & 3) * 4;
            int mg  = m0 + row;
            float4 v = make_float4(0.f, 0.f, 0.f, 0.f);
            if (mg < M) v = *(const float4*)(A + (size_t)mg * K + k0 + c4);
            As[c4+0][row] = v.x; As[c4+1][row] = v.y;
            As[c4+2][row] = v.z; As[c4+3][row] = v.w;
        }
#pragma unroll
        for (int it = 0; it < 2; it++) {
            int f  = tid * 2 + it;
            int kr = f >> 5;
            int c4 = (f & 31) * 4;
            int kg = k0 + kr;
            const float* src = (kg < K1)
                ? (B1p + (size_t)kg * N + n0 + c4)
                : (B2p + (size_t)(kg - K1) * N + n0 + c4);
            *(float4*)&Bs[kr][c4] = *(const float4*)src;
        }
        __syncthreads();

#pragma unroll
        for (int kk = 0; kk < BK; kk++) {
            float4 a0 = *(const float4*)&As[kk][ty*8];
            float4 a1 = *(const float4*)&As[kk][ty*8+4];
            float4 b0 = *(const float4*)&Bs[kk][tx*8];
            float4 b1 = *(const float4*)&Bs[kk][tx*8+4];
            float a[8] = {a0.x,a0.y,a0.z,a0.w,a1.x,a1.y,a1.z,a1.w};
            float b[8] = {b0.x,b0.y,b0.z,b0.w,b1.x,b1.y,b1.z,b1.w};
#pragma unroll
            for (int i = 0; i < 8; i++)
#pragma unroll
                for (int j = 0; j < 8; j++)
                    acc[i][j] = fmaf(a[i], b[j], acc[i][j]);
        }
        __syncthreads();
    }

#pragma unroll
    for (int i = 0; i < 8; i++) {
        int mg = m0 + ty*8 + i;
        if (mg >= M) break;
#pragma unroll
        for (int j = 0; j < 8; j++) {
            int ng = n0 + tx*8 + j;
            float v = acc[i][j];
            if (biasRow) v += biasRow[mg];
            if (relu) v = fmaxf(v, 0.f);
            C[(size_t)mg * N + ng] = v;
        }
    }
}

// ---------------------------------------------------------------------------
// Attention scores + softmax (fast FMA exp)
// ---------------------------------------------------------------------------
__global__ void __launch_bounds__(256)
attn_scores(const float* __restrict__ q, const float* __restrict__ kmat,
            float* __restrict__ E)
{
    extern __shared__ float sc[];      // [16][NN]
    __shared__ float Kv[16][17];
    __shared__ float red[8];

    int b  = blockIdx.y;
    int i0 = blockIdx.x * 16;
    int tid = threadIdx.x;

    const float* qb = q    + (size_t)b * C8V * NN;
    const float* kb = kmat + (size_t)b * C8V * NN;

    {
        int c = tid >> 4, ii = tid & 15;
        Kv[c][ii] = kb[c * NN + i0 + ii];
    }
    __syncthreads();

    const float scale = rsqrtf(128.f);
    for (int j = tid; j < NN; j += 256) {
        float qv[16];
#pragma unroll
        for (int c = 0; c < 16; c++) qv[c] = qb[c * NN + j];
#pragma unroll
        for (int ii = 0; ii < 16; ii++) {
            float s = 0.f;
#pragma unroll
            for (int c = 0; c < 16; c++) s = fmaf(Kv[c][ii], qv[c], s);
            sc[ii * NN + j] = s * scale;
        }
    }
    __syncthreads();

    int w = tid >> 5, l = tid & 31;
    for (int ii = 0; ii < 16; ii++) {
        float* row = sc + ii * NN;
        float m = -1e30f;
        for (int j = tid; j < NN; j += 256) m = fmaxf(m, row[j]);
        for (int o = 16; o; o >>= 1) m = fmaxf(m, __shfl_xor_sync(0xffffffffu, m, o));
        if (l == 0) red[w] = m;
        __syncthreads();
        m = red[0];
#pragma unroll
        for (int t = 1; t < 8; t++) m = fmaxf(m, red[t]);
        float s = 0.f;
        for (int j = tid; j < NN; j += 256) {
            float e = fexp(row[j] - m);
            row[j] = e;
            s += e;
        }
        for (int o = 16; o; o >>= 1) s += __shfl_xor_sync(0xffffffffu, s, o);
        __syncthreads();
        if (l == 0) red[w] = s;
        __syncthreads();
        s = 0.f;
#pragma unroll
        for (int t = 0; t < 8; t++) s += red[t];
        float inv = 1.f / s;
        float* Eb = E + ((size_t)b * NN + i0 + ii) * NN;
        for (int j = tid; j < NN; j += 256) Eb[j] = row[j] * inv;
        __syncthreads();
    }
}

// ---------------------------------------------------------------------------
// Launch
// ---------------------------------------------------------------------------
extern "C" void kernel_launch(void* const* d_in, const int* in_sizes, int n_in,
                              void* d_out, int out_size)
{
    const float* front_x = (const float*)d_in[0];
    const float* bn1_g   = (const float*)d_in[1];
    const float* bn1_b   = (const float*)d_in[2];
    const float* tm1_w1  = (const float*)d_in[3];
    const float* tm1_b1  = (const float*)d_in[4];
    const float* tm1_w2  = (const float*)d_in[5];
    const float* tm1_b2  = (const float*)d_in[6];
    const float* q_w     = (const float*)d_in[7];
    const float* q_b     = (const float*)d_in[8];
    const float* k_w     = (const float*)d_in[9];
    const float* k_b     = (const float*)d_in[10];
    const float* v_w     = (const float*)d_in[11];
    const float* v_b     = (const float*)d_in[12];
    const float* m1_w    = (const float*)d_in[13];
    const float* m1_b    = (const float*)d_in[14];
    const float* bn2_g   = (const float*)d_in[15];
    const float* bn2_b   = (const float*)d_in[16];
    const float* tm2_w1  = (const float*)d_in[17];
    const float* tm2_b1  = (const float*)d_in[18];
    const float* tm2_w2  = (const float*)d_in[19];
    const float* tm2_b2  = (const float*)d_in[20];
    const float* m2_w    = (const float*)d_in[21];
    const float* m2_b    = (const float*)d_in[22];
    float* out = (float*)d_out;

    float *xn, *h, *feat, *vbuf, *Vbuf, *Tbuf, *qb, *kb, *Eb;
    cudaGetSymbolAddress((void**)&xn,   g_xn);
    cudaGetSymbolAddress((void**)&h,    g_h);
    cudaGetSymbolAddress((void**)&feat, g_feat);
    cudaGetSymbolAddress((void**)&vbuf, g_v);
    cudaGetSymbolAddress((void**)&Vbuf, g_V);
    cudaGetSymbolAddress((void**)&Tbuf, g_T);
    cudaGetSymbolAddress((void**)&qb,   g_q);
    cudaGetSymbolAddress((void**)&kb,   g_k);
    cudaGetSymbolAddress((void**)&Eb,   g_E);

    cudaFuncSetAttribute(attn_scores,
                         cudaFuncAttributeMaxDynamicSharedMemorySize,
                         16 * NN * (int)sizeof(float));

    const long long Z0 = 0;
    const long long sFeat = (long long)CCH * NN;
    const long long sQK   = (long long)C8V * NN;
    const long long sE    = (long long)NN * NN;

    dim3 gTM(NN/128, (BSZ*CCH)/128, 1);   // 18 x 16
    dim3 gPV(NN/128, 1, BSZ);             // 18 x 1 x 16
    dim3 gCV(NN/128, 1, BSZ);
    int  nApply = (BCN + 255) / 256;

    // 1. BN1
    bn_stats<<<CCH, 256>>>(front_x);
    bn_apply<<<nApply, 256>>>(front_x, bn1_g, bn1_b, xn);
    // 2. TM1 (tensor cores)
    gemm_tc<<<gTM, 256>>>(xn, tm1_w1, h,    BSZ*CCH, NN, NN, Z0, Z0, Z0, tm1_b1, 1);
    gemm_tc<<<gTM, 256>>>(h,  tm1_w2, feat, BSZ*CCH, NN, NN, Z0, Z0, Z0, tm1_b2, 1);
    // 3. q / k / v 1x1 convs (SIMT, small)
    gemm_nt<<<gCV, 256>>>(q_w, feat, feat, CCH, qb,   C8V, NN, CCH,
                          sFeat, sFeat, sQK,   q_b, 0);
    gemm_nt<<<gCV, 256>>>(k_w, feat, feat, CCH, kb,   C8V, NN, CCH,
                          sFeat, sFeat, sQK,   k_b, 0);
    gemm_nt<<<gCV, 256>>>(v_w, feat, feat, CCH, vbuf, CCH, NN, CCH,
                          sFeat, sFeat, sFeat, v_b, 0);
    // 4. attention scores + softmax -> g_E
    attn_scores<<<dim3(NN/16, BSZ), 256, 16 * NN * sizeof(float)>>>(qb, kb, Eb);
    // 5. V = v @ E^T (tensor cores, batched)
    gemm_tc<<<gPV, 256>>>(vbuf, Eb, Vbuf, CCH, NN, NN,
                          sFeat, sE, sFeat, (const float*)nullptr, 0);
    // 6. m1 conv over concat(feat, V)
    gemm_nt<<<gCV, 256>>>(m1_w, feat, Vbuf, CCH, Tbuf, CCH, NN, 2*CCH,
                          sFeat, sFeat, sFeat, m1_b, 0);
    // 7. BN2
    bn_stats<<<CCH, 256>>>(Tbuf);
    bn_apply<<<nApply, 256>>>(Tbuf, bn2_g, bn2_b, xn);
    // 8. TM2 (tensor cores)
    gemm_tc<<<gTM, 256>>>(xn, tm2_w1, h,    BSZ*CCH, NN, NN, Z0, Z0, Z0, tm2_b1, 1);
    gemm_tc<<<gTM, 256>>>(h,  tm2_w2, feat, BSZ*CCH, NN, NN, Z0, Z0, Z0, tm2_b2, 1);
    // 9. m2 conv over concat(front_res, V) -> output
    gemm_nt<<<gCV, 256>>>(m2_w, feat, Vbuf, CCH, out, CCH, NN, 2*CCH,
                          sFeat, sFeat, sFeat, m2_b, 0);
}